// round 14
// baseline (speedup 1.0000x reference)
#include <cuda_runtime.h>
#include <cuda_bf16.h>
#include <math.h>
#include <stdint.h>

#define D    512
#define BLKR 64
#define NB   128        // batch
#define M    6304       // memory contexts
#define TOPK 50
#define CEPS 1e-8f
#define KSPLIT 4

// ---------------- scratch ----------------
__device__ float g_msq[KSPLIT][M];               // partial sum-of-squares of mc rows
__device__ float g_cosp[KSPLIT][(size_t)NB * M]; // partial dot products
__device__ int   g_tidx[NB * TOPK];
__device__ float g_tw[NB * TOPK];

// ---------------- 1) dot = q @ mc^T via bf16-split mma.sync (HMMA) --------------
// BM=128 (all q rows), BN=64 mc rows per CTA, K=128 per CTA (KSPLIT=4).
// Split fp32 -> bf16 hi + bf16 lo; dot = hi*hi + hi*lo + lo*hi (fp32 acc).
// 256 threads = 8 warps (4 m-warps x 2 n-warps), 32x32 outputs per warp.
#define GBN 64
#define KC  32                       // k per smem stage
#define NSTG ((D / KSPLIT) / KC)     // 4 stages
#define SPAD 40                      // bf16 row stride: 80 B = 20 words -> conflict-free frags
#define NBLK ((M + GBN - 1) / GBN)   // 99

__device__ __forceinline__ void mma_bf16(float* c, const unsigned* a, const unsigned* b) {
    asm volatile(
        "mma.sync.aligned.m16n8k16.row.col.f32.bf16.bf16.f32 "
        "{%0,%1,%2,%3},{%4,%5,%6,%7},{%8,%9},{%0,%1,%2,%3};"
        : "+f"(c[0]), "+f"(c[1]), "+f"(c[2]), "+f"(c[3])
        : "r"(a[0]), "r"(a[1]), "r"(a[2]), "r"(a[3]), "r"(b[0]), "r"(b[1]));
}

__global__ __launch_bounds__(256, 2) void cos_gemm_kernel(const float* __restrict__ q,
                                                          const float* __restrict__ mc) {
    __shared__ __nv_bfloat16 Ah[128][SPAD], Al[128][SPAD];
    __shared__ __nv_bfloat16 Bh[GBN][SPAD], Bl[GBN][SPAD];

    int t = threadIdx.x;
    int lane = t & 31, wid = t >> 5;
    int warp_m = wid & 3;            // m base = warp_m*32
    int warp_n = wid >> 2;           // n base = warp_n*32
    int quad = lane >> 2, tig = lane & 3;
    int n0 = blockIdx.x * GBN;
    int kz = blockIdx.y;
    int kbase = kz * (D / KSPLIT);

    float acc[2][4][4];
#pragma unroll
    for (int mi = 0; mi < 2; mi++)
#pragma unroll
        for (int ni = 0; ni < 4; ni++)
#pragma unroll
            for (int r = 0; r < 4; r++) acc[mi][ni][r] = 0.f;

    float ss0 = 0.f, ss1 = 0.f;      // msq partials for B rows (t>>3) and (t>>3)+32

#pragma unroll
    for (int s = 0; s < NSTG; s++) {
        int k0 = kbase + s * KC;
        // ---- load A (q): 128x32 fp32 -> bf16 hi/lo, 4 float4 per thread ----
#pragma unroll
        for (int i = 0; i < 4; i++) {
            int lin = t + i * 256;
            int row = lin >> 3, c4 = lin & 7;
            float4 v = *(const float4*)(q + (size_t)row * D + k0 + c4 * 4);
            __nv_bfloat162 hxy = __floats2bfloat162_rn(v.x, v.y);
            __nv_bfloat162 hzw = __floats2bfloat162_rn(v.z, v.w);
            __nv_bfloat162 lxy = __floats2bfloat162_rn(v.x - __low2float(hxy), v.y - __high2float(hxy));
            __nv_bfloat162 lzw = __floats2bfloat162_rn(v.z - __low2float(hzw), v.w - __high2float(hzw));
            *(__nv_bfloat162*)&Ah[row][c4 * 4]     = hxy;
            *(__nv_bfloat162*)&Ah[row][c4 * 4 + 2] = hzw;
            *(__nv_bfloat162*)&Al[row][c4 * 4]     = lxy;
            *(__nv_bfloat162*)&Al[row][c4 * 4 + 2] = lzw;
        }
        // ---- load B (mc): 64x32 fp32 -> bf16 hi/lo, 2 float4 per thread; msq ----
#pragma unroll
        for (int i = 0; i < 2; i++) {
            int lin = t + i * 256;
            int n = lin >> 3, c4 = lin & 7;
            int gm = n0 + n;
            float4 v = make_float4(0.f, 0.f, 0.f, 0.f);
            if (gm < M) v = *(const float4*)(mc + (size_t)gm * D + k0 + c4 * 4);
            float sq = v.x * v.x + v.y * v.y + v.z * v.z + v.w * v.w;
            if (i == 0) ss0 += sq; else ss1 += sq;
            __nv_bfloat162 hxy = __floats2bfloat162_rn(v.x, v.y);
            __nv_bfloat162 hzw = __floats2bfloat162_rn(v.z, v.w);
            __nv_bfloat162 lxy = __floats2bfloat162_rn(v.x - __low2float(hxy), v.y - __high2float(hxy));
            __nv_bfloat162 lzw = __floats2bfloat162_rn(v.z - __low2float(hzw), v.w - __high2float(hzw));
            *(__nv_bfloat162*)&Bh[n][c4 * 4]     = hxy;
            *(__nv_bfloat162*)&Bh[n][c4 * 4 + 2] = hzw;
            *(__nv_bfloat162*)&Bl[n][c4 * 4]     = lxy;
            *(__nv_bfloat162*)&Bl[n][c4 * 4 + 2] = lzw;
        }
        __syncthreads();

        // ---- MMA over 2 k16 steps ----
#pragma unroll
        for (int ks = 0; ks < 2; ks++) {
            int koff = ks * 16;
            unsigned ah[2][4], al[2][4], bh[4][2], bl[4][2];
#pragma unroll
            for (int mi = 0; mi < 2; mi++) {
                int r = warp_m * 32 + mi * 16 + quad;
                int kk = koff + tig * 2;
                ah[mi][0] = *(const unsigned*)&Ah[r][kk];
                ah[mi][1] = *(const unsigned*)&Ah[r + 8][kk];
                ah[mi][2] = *(const unsigned*)&Ah[r][kk + 8];
                ah[mi][3] = *(const unsigned*)&Ah[r + 8][kk + 8];
                al[mi][0] = *(const unsigned*)&Al[r][kk];
                al[mi][1] = *(const unsigned*)&Al[r + 8][kk];
                al[mi][2] = *(const unsigned*)&Al[r][kk + 8];
                al[mi][3] = *(const unsigned*)&Al[r + 8][kk + 8];
            }
#pragma unroll
            for (int ni = 0; ni < 4; ni++) {
                int n = warp_n * 32 + ni * 8 + quad;
                int kk = koff + tig * 2;
                bh[ni][0] = *(const unsigned*)&Bh[n][kk];
                bh[ni][1] = *(const unsigned*)&Bh[n][kk + 8];
                bl[ni][0] = *(const unsigned*)&Bl[n][kk];
                bl[ni][1] = *(const unsigned*)&Bl[n][kk + 8];
            }
#pragma unroll
            for (int mi = 0; mi < 2; mi++)
#pragma unroll
                for (int ni = 0; ni < 4; ni++) {
                    mma_bf16(acc[mi][ni], ah[mi], bh[ni]);   // hi*hi
                    mma_bf16(acc[mi][ni], ah[mi], bl[ni]);   // hi*lo
                    mma_bf16(acc[mi][ni], al[mi], bh[ni]);   // lo*hi
                }
        }
        __syncthreads();
    }

    // ---- msq: reduce over 8 loader lanes sharing a row (lanes differ in t&7) ----
    ss0 += __shfl_xor_sync(0xffffffffu, ss0, 1);
    ss0 += __shfl_xor_sync(0xffffffffu, ss0, 2);
    ss0 += __shfl_xor_sync(0xffffffffu, ss0, 4);
    ss1 += __shfl_xor_sync(0xffffffffu, ss1, 1);
    ss1 += __shfl_xor_sync(0xffffffffu, ss1, 2);
    ss1 += __shfl_xor_sync(0xffffffffu, ss1, 4);
    if ((t & 7) == 0) {
        int n = t >> 3;
        if (n0 + n < M)      g_msq[kz][n0 + n] = ss0;
        if (n0 + n + 32 < M) g_msq[kz][n0 + n + 32] = ss1;
    }

    // ---- epilogue: c0,c1 -> (row, col), c2,c3 -> (row+8, col) ----
    float* dst = &g_cosp[kz][0];
#pragma unroll
    for (int mi = 0; mi < 2; mi++) {
        int r = warp_m * 32 + mi * 16 + quad;
#pragma unroll
        for (int ni = 0; ni < 4; ni++) {
            int col = n0 + warp_n * 32 + ni * 8 + tig * 2;
            if (col < M) {
                *(float2*)&dst[(size_t)r * M + col]       = make_float2(acc[mi][ni][0], acc[mi][ni][1]);
                *(float2*)&dst[(size_t)(r + 8) * M + col] = make_float2(acc[mi][ni][2], acc[mi][ni][3]);
            }
        }
    }
}

// ---------------- 2) radix-select top-50 + softmax (norms fused in) ----------------
#define TIECAP 256
#define TKT 512     // topk threads

__device__ __forceinline__ unsigned key_of(float v) {
    unsigned u = __float_as_uint(v);
    return (u & 0x80000000u) ? ~u : (u | 0x80000000u);   // monotonic flip
}
__device__ __forceinline__ float val_of(unsigned k) {
    unsigned u = (k & 0x80000000u) ? (k & 0x7fffffffu) : ~k;
    return __uint_as_float(u);
}

__global__ __launch_bounds__(TKT) void topk_kernel(const float* __restrict__ q) {
    __shared__ unsigned keys[M];            // 25.2 KB
    __shared__ int suf[257];                // suffix counts (suf[256]=0)
    __shared__ unsigned s_prefix;
    __shared__ int s_remaining;
    __shared__ int s_gtcnt, s_tiecnt;
    __shared__ unsigned gt_k[64];
    __shared__ int gt_i[64];
    __shared__ int tie_i[TIECAP];
    __shared__ int fin_idx[TOPK];
    __shared__ float fin_val[TOPK];
    __shared__ float fin_e[TOPK];
    __shared__ float s_sum;
    __shared__ float s_qred[4];
    __shared__ float s_qi;

    int b = blockIdx.x, t = threadIdx.x;

    // q row norm for this batch
    {
        float ssq = 0.f;
        if (t < 128) {
            float4 v = ((const float4*)(q + (size_t)b * D))[t];
            ssq = v.x * v.x + v.y * v.y + v.z * v.z + v.w * v.w;
        }
#pragma unroll
        for (int o = 16; o > 0; o >>= 1) ssq += __shfl_xor_sync(0xffffffffu, ssq, o);
        if (t < 128 && (t & 31) == 0) s_qred[t >> 5] = ssq;
        __syncthreads();
        if (t == 0) {
            float tot = (s_qred[0] + s_qred[1]) + (s_qred[2] + s_qred[3]);
            s_qi = 1.0f / fmaxf(sqrtf(tot), CEPS);
        }
        __syncthreads();
    }
    float qi = s_qi;

    for (int i = t; i < M; i += TKT) {
        float d = (g_cosp[0][(size_t)b * M + i] + g_cosp[1][(size_t)b * M + i])
                + (g_cosp[2][(size_t)b * M + i] + g_cosp[3][(size_t)b * M + i]);
        float m = (g_msq[0][i] + g_msq[1][i]) + (g_msq[2][i] + g_msq[3][i]);
        float minv = 1.0f / fmaxf(sqrtf(m), CEPS);
        keys[i] = key_of(d * qi * minv);
    }
    if (t == 0) { s_prefix = 0u; s_remaining = TOPK; s_gtcnt = 0; s_tiecnt = 0; }
    __syncthreads();

#pragma unroll
    for (int level = 0; level < 4; level++) {
        int shift = 24 - level * 8;
        if (t < 257) suf[t] = 0;
        __syncthreads();
        unsigned pfx = s_prefix;
        for (int i = t; i < M; i += TKT) {
            unsigned k = keys[i];
            bool in = (level == 0) || ((k >> (shift + 8)) == pfx);
            if (in) atomicAdd(&suf[(k >> shift) & 255], 1);
        }
        __syncthreads();
        // warp 0: suffix scan of 256 bins (8 bins/lane + shfl suffix over lanes)
        if (t < 32) {
            int loc[8];
            int run = 0;
#pragma unroll
            for (int j = 7; j >= 0; j--) { run += suf[t * 8 + j]; loc[j] = run; }
            int x = run;   // chunk sum
#pragma unroll
            for (int o = 1; o < 32; o <<= 1) {
                int y = __shfl_down_sync(0xffffffffu, x, o);
                if (t + o < 32) x += y;
            }
            int excl = x - run;   // sum of chunks above this one
#pragma unroll
            for (int j = 0; j < 8; j++) suf[t * 8 + j] = loc[j] + excl;
        }
        __syncthreads();
        int rem = s_remaining;
        if (t < 256 && suf[t] >= rem && suf[t + 1] < rem) {
            s_prefix = (s_prefix << 8) | (unsigned)t;
            s_remaining = rem - suf[t + 1];
        }
        __syncthreads();
    }

    unsigned T = s_prefix;               // exact 50th-largest key
    int rem = s_remaining;
    for (int i = t; i < M; i += TKT) {
        unsigned k = keys[i];
        if (k > T) {
            int p = atomicAdd(&s_gtcnt, 1);
            gt_k[p] = k; gt_i[p] = i;
        } else if (k == T) {
            int p = atomicAdd(&s_tiecnt, 1);
            if (p < TIECAP) tie_i[p] = i;
        }
    }
    __syncthreads();
    int ngt = s_gtcnt;                   // == TOPK - rem
    int ntie = min(s_tiecnt, TIECAP);
    if (t < ngt) {
        unsigned mk = gt_k[t]; int mi = gt_i[t];
        int rank = 0;
        for (int j = 0; j < ngt; j++) {
            unsigned ok = gt_k[j]; int oi = gt_i[j];
            if (ok > mk || (ok == mk && oi < mi)) rank++;
        }
        fin_idx[rank] = mi;
        fin_val[rank] = val_of(mk);
    }
    if (t < ntie) {
        int mi = tie_i[t];
        int rank = 0;
        for (int j = 0; j < ntie; j++) if (tie_i[j] < mi) rank++;
        if (rank < rem) {
            fin_idx[ngt + rank] = mi;
            fin_val[ngt + rank] = val_of(T);
        }
    }
    __syncthreads();
    if (t < TOPK) fin_e[t] = expf(fin_val[t] - fin_val[0]);
    __syncthreads();
    if (t == 0) {
        float s = 0.f;
        for (int kk = 0; kk < TOPK; kk++) s += fin_e[kk];
        s_sum = 1.0f / s;
    }
    __syncthreads();
    if (t < TOPK) {
        g_tidx[b * TOPK + t] = fin_idx[t];
        g_tw[b * TOPK + t]   = fin_e[t] * s_sum;
    }
}

// ---------------- 3) weighted block gather + blend (l-major, MLP batched) ----
__global__ __launch_bounds__(128) void gather_kernel(const float* __restrict__ enc,
                                                     const float* __restrict__ fp,
                                                     const float* __restrict__ weight,
                                                     float* __restrict__ out) {
    __shared__ const float4* s_p[TOPK];
    __shared__ float s_w[TOPK];
    int b = blockIdx.x & (NB - 1);     // fast dim: batch -> concurrent CTAs share l
    int l = blockIdx.x >> 7;           // slow dim: row within block
    int t = threadIdx.x;               // 128 threads x float4 = 512 floats
    if (t < TOPK) {
        s_p[t] = (const float4*)(fp + ((size_t)g_tidx[b * TOPK + t] * BLKR + l) * D);
        s_w[t] = g_tw[b * TOPK + t];
    }
    __syncthreads();

    float ax = 0.f, ay = 0.f, az = 0.f, aw = 0.f;
#pragma unroll
    for (int kk = 0; kk < TOPK; kk += 10) {
        float4 v[10];
#pragma unroll
        for (int u = 0; u < 10; u++) v[u] = s_p[kk + u][t];
#pragma unroll
        for (int u = 0; u < 10; u++) {
            float w = s_w[kk + u];
            ax += w * v[u].x; ay += w * v[u].y; az += w * v[u].z; aw += w * v[u].w;
        }
    }

    float wm = weight[0];
    float em = 1.f - wm;
    size_t off = ((size_t)b * BLKR + l) * D;
    float4 e = ((const float4*)(enc + off))[t];
    float4 o;
    o.x = ax * wm + e.x * em;
    o.y = ay * wm + e.y * em;
    o.z = az * wm + e.z * em;
    o.w = aw * wm + e.w * em;
    ((float4*)(out + off))[t] = o;
}

// ---------------- launch ----------------
extern "C" void kernel_launch(void* const* d_in, const int* in_sizes, int n_in,
                              void* d_out, int out_size) {
    const float* enc = (const float*)d_in[0];   // [128, 64, 512]
    const float* q   = (const float*)d_in[1];   // [128, 512]
    const float* mc  = (const float*)d_in[2];   // [6304, 512]
    const float* fp  = (const float*)d_in[3];   // [403456, 512]
    const float* w   = (const float*)d_in[4];   // [1]
    float* out = (float*)d_out;                 // [128, 64, 512]

    cos_gemm_kernel<<<dim3(NBLK, KSPLIT), 256>>>(q, mc);
    topk_kernel<<<NB, TKT>>>(q);
    gather_kernel<<<NB * BLKR, 128>>>(enc, fp, w, out);
}

// round 15
// speedup vs baseline: 1.0187x; 1.0187x over previous
#include <cuda_runtime.h>
#include <cuda_bf16.h>
#include <math.h>
#include <stdint.h>

#define D    512
#define BLKR 64
#define NB   128        // batch
#define M    6304       // memory contexts
#define TOPK 50
#define CEPS 1e-8f
#define KSPLIT 4

// ---------------- scratch ----------------
__device__ float g_msq[KSPLIT][M];               // partial sum-of-squares of mc rows
__device__ float g_cosp[KSPLIT][(size_t)NB * M]; // partial dot products
__device__ int   g_tidx[NB * TOPK];
__device__ float g_tw[NB * TOPK];

// ---------------- 1) dot = q @ mc^T via bf16-split mma.sync, pipelined ---------
// BM=128, BN=64, KC=16 per stage, 8 stages (KSPLIT=4). Double-buffered smem:
// LDG(s+1) overlaps MMA(s); convert+STS lands in the other buffer; 1 bar/stage.
// Split fp32 -> bf16 hi + lo; dot = hi*hi + hi*lo + lo*hi (fp32 acc).
// 256 threads = 8 warps (4 m x 2 n), 32x32 outputs per warp.
#define GBN 64
#define KC  16
#define NSTG ((D / KSPLIT) / KC)     // 8 stages
#define SP16 24                      // row stride (bf16): 12 words -> frag-conflict-free
#define NBLK ((M + GBN - 1) / GBN)   // 99

__device__ __forceinline__ void mma_bf16(float* c, const unsigned* a, const unsigned* b) {
    asm volatile(
        "mma.sync.aligned.m16n8k16.row.col.f32.bf16.bf16.f32 "
        "{%0,%1,%2,%3},{%4,%5,%6,%7},{%8,%9},{%0,%1,%2,%3};"
        : "+f"(c[0]), "+f"(c[1]), "+f"(c[2]), "+f"(c[3])
        : "r"(a[0]), "r"(a[1]), "r"(a[2]), "r"(a[3]), "r"(b[0]), "r"(b[1]));
}

__global__ __launch_bounds__(256, 2) void cos_gemm_kernel(const float* __restrict__ q,
                                                          const float* __restrict__ mc) {
    __shared__ __nv_bfloat16 Ah[2][128][SP16], Al[2][128][SP16];  // 24.6 KB
    __shared__ __nv_bfloat16 Bh[2][GBN][SP16], Bl[2][GBN][SP16];  // 12.3 KB

    int t = threadIdx.x;
    int lane = t & 31, wid = t >> 5;
    int warp_m = wid & 3;            // m base = warp_m*32
    int warp_n = wid >> 2;           // n base = warp_n*32
    int quad = lane >> 2, tig = lane & 3;
    int n0 = blockIdx.x * GBN;
    int kz = blockIdx.y;
    int kbase = kz * (D / KSPLIT);

    // loader coords: A chunks (512 = 128 rows x 4 chunks), B chunks (256 = 64 x 4)
    int ar0 = t >> 2, ac = t & 3;            // A chunk 0: row t>>2
    int ar1 = (t + 256) >> 2;                // A chunk 1: row (t+256)>>2
    int br = t >> 2, bc = t & 3;             // B: row t>>2 (0..63), chunk t&3
    int bg = n0 + br;

    float acc[2][4][4];
#pragma unroll
    for (int mi = 0; mi < 2; mi++)
#pragma unroll
        for (int ni = 0; ni < 4; ni++)
#pragma unroll
            for (int r = 0; r < 4; r++) acc[mi][ni][r] = 0.f;

    float ss = 0.f;                  // msq partial for B row br
    float4 pa0, pa1, pb;

    // ---- prologue: load + convert stage 0 into buf 0 ----
    {
        int k0 = kbase;
        pa0 = *(const float4*)(q + (size_t)ar0 * D + k0 + ac * 4);
        pa1 = *(const float4*)(q + (size_t)ar1 * D + k0 + ac * 4);
        pb = make_float4(0.f, 0.f, 0.f, 0.f);
        if (bg < M) pb = *(const float4*)(mc + (size_t)bg * D + k0 + bc * 4);
    }

#pragma unroll
    for (int s = 0; s < NSTG; s++) {
        int buf = s & 1;
        // ---- convert + STS current staged registers into buf ----
        {
            __nv_bfloat162 h0 = __floats2bfloat162_rn(pa0.x, pa0.y);
            __nv_bfloat162 h1 = __floats2bfloat162_rn(pa0.z, pa0.w);
            *(__nv_bfloat162*)&Ah[buf][ar0][ac * 4]     = h0;
            *(__nv_bfloat162*)&Ah[buf][ar0][ac * 4 + 2] = h1;
            *(__nv_bfloat162*)&Al[buf][ar0][ac * 4] =
                __floats2bfloat162_rn(pa0.x - __low2float(h0), pa0.y - __high2float(h0));
            *(__nv_bfloat162*)&Al[buf][ar0][ac * 4 + 2] =
                __floats2bfloat162_rn(pa0.z - __low2float(h1), pa0.w - __high2float(h1));
            __nv_bfloat162 h2 = __floats2bfloat162_rn(pa1.x, pa1.y);
            __nv_bfloat162 h3 = __floats2bfloat162_rn(pa1.z, pa1.w);
            *(__nv_bfloat162*)&Ah[buf][ar1][ac * 4]     = h2;
            *(__nv_bfloat162*)&Ah[buf][ar1][ac * 4 + 2] = h3;
            *(__nv_bfloat162*)&Al[buf][ar1][ac * 4] =
                __floats2bfloat162_rn(pa1.x - __low2float(h2), pa1.y - __high2float(h2));
            *(__nv_bfloat162*)&Al[buf][ar1][ac * 4 + 2] =
                __floats2bfloat162_rn(pa1.z - __low2float(h3), pa1.w - __high2float(h3));
            ss += pb.x * pb.x + pb.y * pb.y + pb.z * pb.z + pb.w * pb.w;
            __nv_bfloat162 g0 = __floats2bfloat162_rn(pb.x, pb.y);
            __nv_bfloat162 g1 = __floats2bfloat162_rn(pb.z, pb.w);
            *(__nv_bfloat162*)&Bh[buf][br][bc * 4]     = g0;
            *(__nv_bfloat162*)&Bh[buf][br][bc * 4 + 2] = g1;
            *(__nv_bfloat162*)&Bl[buf][br][bc * 4] =
                __floats2bfloat162_rn(pb.x - __low2float(g0), pb.y - __high2float(g0));
            *(__nv_bfloat162*)&Bl[buf][br][bc * 4 + 2] =
                __floats2bfloat162_rn(pb.z - __low2float(g1), pb.w - __high2float(g1));
        }
        __syncthreads();

        // ---- issue LDG for stage s+1 (overlaps the MMA below) ----
        if (s + 1 < NSTG) {
            int k0 = kbase + (s + 1) * KC;
            pa0 = *(const float4*)(q + (size_t)ar0 * D + k0 + ac * 4);
            pa1 = *(const float4*)(q + (size_t)ar1 * D + k0 + ac * 4);
            pb = make_float4(0.f, 0.f, 0.f, 0.f);
            if (bg < M) pb = *(const float4*)(mc + (size_t)bg * D + k0 + bc * 4);
        }

        // ---- MMA on buf (one k16 step) ----
        {
            int kk = tig * 2;
            unsigned ah[2][4], al[2][4], bh[4][2], bl[4][2];
#pragma unroll
            for (int mi = 0; mi < 2; mi++) {
                int r = warp_m * 32 + mi * 16 + quad;
                ah[mi][0] = *(const unsigned*)&Ah[buf][r][kk];
                ah[mi][1] = *(const unsigned*)&Ah[buf][r + 8][kk];
                ah[mi][2] = *(const unsigned*)&Ah[buf][r][kk + 8];
                ah[mi][3] = *(const unsigned*)&Ah[buf][r + 8][kk + 8];
                al[mi][0] = *(const unsigned*)&Al[buf][r][kk];
                al[mi][1] = *(const unsigned*)&Al[buf][r + 8][kk];
                al[mi][2] = *(const unsigned*)&Al[buf][r][kk + 8];
                al[mi][3] = *(const unsigned*)&Al[buf][r + 8][kk + 8];
            }
#pragma unroll
            for (int ni = 0; ni < 4; ni++) {
                int n = warp_n * 32 + ni * 8 + quad;
                bh[ni][0] = *(const unsigned*)&Bh[buf][n][kk];
                bh[ni][1] = *(const unsigned*)&Bh[buf][n][kk + 8];
                bl[ni][0] = *(const unsigned*)&Bl[buf][n][kk];
                bl[ni][1] = *(const unsigned*)&Bl[buf][n][kk + 8];
            }
#pragma unroll
            for (int mi = 0; mi < 2; mi++)
#pragma unroll
                for (int ni = 0; ni < 4; ni++) {
                    mma_bf16(acc[mi][ni], ah[mi], bh[ni]);   // hi*hi
                    mma_bf16(acc[mi][ni], ah[mi], bl[ni]);   // hi*lo
                    mma_bf16(acc[mi][ni], al[mi], bh[ni]);   // lo*hi
                }
        }
        // NOTE: next iteration's STS targets buf^1, whose readers finished at the
        // bar above; the bar at the top of next iteration orders STS before reads.
    }
    __syncthreads();

    // ---- msq: reduce over 4 loader lanes sharing B row (lanes differ in t&3) ----
    ss += __shfl_xor_sync(0xffffffffu, ss, 1);
    ss += __shfl_xor_sync(0xffffffffu, ss, 2);
    if (bc == 0 && bg < M) g_msq[kz][bg] = ss;

    // ---- epilogue: c0,c1 -> (row, col), c2,c3 -> (row+8, col) ----
    float* dst = &g_cosp[kz][0];
#pragma unroll
    for (int mi = 0; mi < 2; mi++) {
        int r = warp_m * 32 + mi * 16 + quad;
#pragma unroll
        for (int ni = 0; ni < 4; ni++) {
            int col = n0 + warp_n * 32 + ni * 8 + tig * 2;
            if (col < M) {
                *(float2*)&dst[(size_t)r * M + col]       = make_float2(acc[mi][ni][0], acc[mi][ni][1]);
                *(float2*)&dst[(size_t)(r + 8) * M + col] = make_float2(acc[mi][ni][2], acc[mi][ni][3]);
            }
        }
    }
}

// ---------------- 2) radix-select top-50 + softmax (norms fused in) ----------------
#define TIECAP 256
#define TKT 512     // topk threads

__device__ __forceinline__ unsigned key_of(float v) {
    unsigned u = __float_as_uint(v);
    return (u & 0x80000000u) ? ~u : (u | 0x80000000u);   // monotonic flip
}
__device__ __forceinline__ float val_of(unsigned k) {
    unsigned u = (k & 0x80000000u) ? (k & 0x7fffffffu) : ~k;
    return __uint_as_float(u);
}

__global__ __launch_bounds__(TKT) void topk_kernel(const float* __restrict__ q) {
    __shared__ unsigned keys[M];            // 25.2 KB
    __shared__ int suf[257];                // suffix counts (suf[256]=0)
    __shared__ unsigned s_prefix;
    __shared__ int s_remaining;
    __shared__ int s_gtcnt, s_tiecnt;
    __shared__ unsigned gt_k[64];
    __shared__ int gt_i[64];
    __shared__ int tie_i[TIECAP];
    __shared__ int fin_idx[TOPK];
    __shared__ float fin_val[TOPK];
    __shared__ float fin_e[TOPK];
    __shared__ float s_sum;
    __shared__ float s_qred[4];
    __shared__ float s_qi;

    int b = blockIdx.x, t = threadIdx.x;

    // q row norm for this batch
    {
        float ssq = 0.f;
        if (t < 128) {
            float4 v = ((const float4*)(q + (size_t)b * D))[t];
            ssq = v.x * v.x + v.y * v.y + v.z * v.z + v.w * v.w;
        }
#pragma unroll
        for (int o = 16; o > 0; o >>= 1) ssq += __shfl_xor_sync(0xffffffffu, ssq, o);
        if (t < 128 && (t & 31) == 0) s_qred[t >> 5] = ssq;
        __syncthreads();
        if (t == 0) {
            float tot = (s_qred[0] + s_qred[1]) + (s_qred[2] + s_qred[3]);
            s_qi = 1.0f / fmaxf(sqrtf(tot), CEPS);
        }
        __syncthreads();
    }
    float qi = s_qi;

    for (int i = t; i < M; i += TKT) {
        float d = (g_cosp[0][(size_t)b * M + i] + g_cosp[1][(size_t)b * M + i])
                + (g_cosp[2][(size_t)b * M + i] + g_cosp[3][(size_t)b * M + i]);
        float m = (g_msq[0][i] + g_msq[1][i]) + (g_msq[2][i] + g_msq[3][i]);
        float minv = 1.0f / fmaxf(sqrtf(m), CEPS);
        keys[i] = key_of(d * qi * minv);
    }
    if (t == 0) { s_prefix = 0u; s_remaining = TOPK; s_gtcnt = 0; s_tiecnt = 0; }
    __syncthreads();

#pragma unroll
    for (int level = 0; level < 4; level++) {
        int shift = 24 - level * 8;
        if (t < 257) suf[t] = 0;
        __syncthreads();
        unsigned pfx = s_prefix;
        for (int i = t; i < M; i += TKT) {
            unsigned k = keys[i];
            bool in = (level == 0) || ((k >> (shift + 8)) == pfx);
            if (in) atomicAdd(&suf[(k >> shift) & 255], 1);
        }
        __syncthreads();
        // warp 0: suffix scan of 256 bins (8 bins/lane + shfl suffix over lanes)
        if (t < 32) {
            int loc[8];
            int run = 0;
#pragma unroll
            for (int j = 7; j >= 0; j--) { run += suf[t * 8 + j]; loc[j] = run; }
            int x = run;   // chunk sum
#pragma unroll
            for (int o = 1; o < 32; o <<= 1) {
                int y = __shfl_down_sync(0xffffffffu, x, o);
                if (t + o < 32) x += y;
            }
            int excl = x - run;   // sum of chunks above this one
#pragma unroll
            for (int j = 0; j < 8; j++) suf[t * 8 + j] = loc[j] + excl;
        }
        __syncthreads();
        int rem = s_remaining;
        if (t < 256 && suf[t] >= rem && suf[t + 1] < rem) {
            s_prefix = (s_prefix << 8) | (unsigned)t;
            s_remaining = rem - suf[t + 1];
        }
        __syncthreads();
    }

    unsigned T = s_prefix;               // exact 50th-largest key
    int rem = s_remaining;
    for (int i = t; i < M; i += TKT) {
        unsigned k = keys[i];
        if (k > T) {
            int p = atomicAdd(&s_gtcnt, 1);
            gt_k[p] = k; gt_i[p] = i;
        } else if (k == T) {
            int p = atomicAdd(&s_tiecnt, 1);
            if (p < TIECAP) tie_i[p] = i;
        }
    }
    __syncthreads();
    int ngt = s_gtcnt;                   // == TOPK - rem
    int ntie = min(s_tiecnt, TIECAP);
    if (t < ngt) {
        unsigned mk = gt_k[t]; int mi = gt_i[t];
        int rank = 0;
        for (int j = 0; j < ngt; j++) {
            unsigned ok = gt_k[j]; int oi = gt_i[j];
            if (ok > mk || (ok == mk && oi < mi)) rank++;
        }
        fin_idx[rank] = mi;
        fin_val[rank] = val_of(mk);
    }
    if (t < ntie) {
        int mi = tie_i[t];
        int rank = 0;
        for (int j = 0; j < ntie; j++) if (tie_i[j] < mi) rank++;
        if (rank < rem) {
            fin_idx[ngt + rank] = mi;
            fin_val[ngt + rank] = val_of(T);
        }
    }
    __syncthreads();
    if (t < TOPK) fin_e[t] = expf(fin_val[t] - fin_val[0]);
    __syncthreads();
    if (t == 0) {
        float s = 0.f;
        for (int kk = 0; kk < TOPK; kk++) s += fin_e[kk];
        s_sum = 1.0f / s;
    }
    __syncthreads();
    if (t < TOPK) {
        g_tidx[b * TOPK + t] = fin_idx[t];
        g_tw[b * TOPK + t]   = fin_e[t] * s_sum;
    }
}

// ---------------- 3) weighted block gather + blend (l-major, MLP batched) ----
__global__ __launch_bounds__(128) void gather_kernel(const float* __restrict__ enc,
                                                     const float* __restrict__ fp,
                                                     const float* __restrict__ weight,
                                                     float* __restrict__ out) {
    __shared__ const float4* s_p[TOPK];
    __shared__ float s_w[TOPK];
    int b = blockIdx.x & (NB - 1);     // fast dim: batch -> concurrent CTAs share l
    int l = blockIdx.x >> 7;           // slow dim: row within block
    int t = threadIdx.x;               // 128 threads x float4 = 512 floats
    if (t < TOPK) {
        s_p[t] = (const float4*)(fp + ((size_t)g_tidx[b * TOPK + t] * BLKR + l) * D);
        s_w[t] = g_tw[b * TOPK + t];
    }
    __syncthreads();

    float ax = 0.f, ay = 0.f, az = 0.f, aw = 0.f;
#pragma unroll
    for (int kk = 0; kk < TOPK; kk += 10) {
        float4 v[10];
#pragma unroll
        for (int u = 0; u < 10; u++) v[u] = s_p[kk + u][t];
#pragma unroll
        for (int u = 0; u < 10; u++) {
            float w = s_w[kk + u];
            ax += w * v[u].x; ay += w * v[u].y; az += w * v[u].z; aw += w * v[u].w;
        }
    }

    float wm = weight[0];
    float em = 1.f - wm;
    size_t off = ((size_t)b * BLKR + l) * D;
    float4 e = ((const float4*)(enc + off))[t];
    float4 o;
    o.x = ax * wm + e.x * em;
    o.y = ay * wm + e.y * em;
    o.z = az * wm + e.z * em;
    o.w = aw * wm + e.w * em;
    ((float4*)(out + off))[t] = o;
}

// ---------------- launch ----------------
extern "C" void kernel_launch(void* const* d_in, const int* in_sizes, int n_in,
                              void* d_out, int out_size) {
    const float* enc = (const float*)d_in[0];   // [128, 64, 512]
    const float* q   = (const float*)d_in[1];   // [128, 512]
    const float* mc  = (const float*)d_in[2];   // [6304, 512]
    const float* fp  = (const float*)d_in[3];   // [403456, 512]
    const float* w   = (const float*)d_in[4];   // [1]
    float* out = (float*)d_out;                 // [128, 64, 512]

    cos_gemm_kernel<<<dim3(NBLK, KSPLIT), 256>>>(q, mc);
    topk_kernel<<<NB, TKT>>>(q);
    gather_kernel<<<NB * BLKR, 128>>>(enc, fp, w, out);
}

// round 16
// speedup vs baseline: 1.0293x; 1.0104x over previous
#include <cuda_runtime.h>
#include <cuda_bf16.h>
#include <math.h>
#include <stdint.h>

#define D    512
#define BLKR 64
#define NB   128        // batch
#define M    6304       // memory contexts
#define TOPK 50
#define CEPS 1e-8f
#define KSPLIT 4

// ---------------- scratch ----------------
__device__ float g_msq[KSPLIT][M];               // partial sum-of-squares of mc rows
__device__ float g_cosp[KSPLIT][(size_t)NB * M]; // partial dot products
__device__ int   g_tidx[NB * TOPK];
__device__ float g_tw[NB * TOPK];

// ---------------- 1) dot = q @ mc^T via bf16-split mma.sync, pipelined ---------
// BM=128, BN=64, KC=16 per stage, 8 stages (KSPLIT=4). Double-buffered smem:
// LDG(s+1) issued before the barrier so it overlaps bar-wait + MMA(s).
// Split fp32 -> bf16 hi + lo; dot = hi*hi + hi*lo + lo*hi (fp32 acc).
// 256 threads = 8 warps (4 m x 2 n), 32x32 outputs per warp.
#define GBN 64
#define KC  16
#define NSTG ((D / KSPLIT) / KC)     // 8 stages
#define SP16 24                      // row stride (bf16): 12 words -> frag-conflict-free
#define NBLK ((M + GBN - 1) / GBN)   // 99

__device__ __forceinline__ void mma_bf16(float* c, const unsigned* a, const unsigned* b) {
    asm volatile(
        "mma.sync.aligned.m16n8k16.row.col.f32.bf16.bf16.f32 "
        "{%0,%1,%2,%3},{%4,%5,%6,%7},{%8,%9},{%0,%1,%2,%3};"
        : "+f"(c[0]), "+f"(c[1]), "+f"(c[2]), "+f"(c[3])
        : "r"(a[0]), "r"(a[1]), "r"(a[2]), "r"(a[3]), "r"(b[0]), "r"(b[1]));
}

__global__ __launch_bounds__(256, 2) void cos_gemm_kernel(const float* __restrict__ q,
                                                          const float* __restrict__ mc) {
    __shared__ __nv_bfloat16 Ah[2][128][SP16], Al[2][128][SP16];  // 24.6 KB
    __shared__ __nv_bfloat16 Bh[2][GBN][SP16], Bl[2][GBN][SP16];  // 12.3 KB

    int t = threadIdx.x;
    int lane = t & 31, wid = t >> 5;
    int warp_m = wid & 3;            // m base = warp_m*32
    int warp_n = wid >> 2;           // n base = warp_n*32
    int quad = lane >> 2, tig = lane & 3;
    int n0 = blockIdx.x * GBN;
    int kz = blockIdx.y;
    int kbase = kz * (D / KSPLIT);

    int ar0 = t >> 2, ac = t & 3;            // A chunk 0: row t>>2
    int ar1 = (t + 256) >> 2;                // A chunk 1: row (t+256)>>2
    int br = t >> 2, bc = t & 3;             // B: row t>>2 (0..63), chunk t&3
    int bg = n0 + br;

    float acc[2][4][4];
#pragma unroll
    for (int mi = 0; mi < 2; mi++)
#pragma unroll
        for (int ni = 0; ni < 4; ni++)
#pragma unroll
            for (int r = 0; r < 4; r++) acc[mi][ni][r] = 0.f;

    float ss = 0.f;                  // msq partial for B row br
    float4 pa0, pa1, pb;

    // ---- prologue: load stage 0 ----
    {
        int k0 = kbase;
        pa0 = *(const float4*)(q + (size_t)ar0 * D + k0 + ac * 4);
        pa1 = *(const float4*)(q + (size_t)ar1 * D + k0 + ac * 4);
        pb = make_float4(0.f, 0.f, 0.f, 0.f);
        if (bg < M) pb = *(const float4*)(mc + (size_t)bg * D + k0 + bc * 4);
    }

#pragma unroll
    for (int s = 0; s < NSTG; s++) {
        int buf = s & 1;
        // ---- convert + STS staged registers into buf ----
        {
            __nv_bfloat162 h0 = __floats2bfloat162_rn(pa0.x, pa0.y);
            __nv_bfloat162 h1 = __floats2bfloat162_rn(pa0.z, pa0.w);
            *(__nv_bfloat162*)&Ah[buf][ar0][ac * 4]     = h0;
            *(__nv_bfloat162*)&Ah[buf][ar0][ac * 4 + 2] = h1;
            *(__nv_bfloat162*)&Al[buf][ar0][ac * 4] =
                __floats2bfloat162_rn(pa0.x - __low2float(h0), pa0.y - __high2float(h0));
            *(__nv_bfloat162*)&Al[buf][ar0][ac * 4 + 2] =
                __floats2bfloat162_rn(pa0.z - __low2float(h1), pa0.w - __high2float(h1));
            __nv_bfloat162 h2 = __floats2bfloat162_rn(pa1.x, pa1.y);
            __nv_bfloat162 h3 = __floats2bfloat162_rn(pa1.z, pa1.w);
            *(__nv_bfloat162*)&Ah[buf][ar1][ac * 4]     = h2;
            *(__nv_bfloat162*)&Ah[buf][ar1][ac * 4 + 2] = h3;
            *(__nv_bfloat162*)&Al[buf][ar1][ac * 4] =
                __floats2bfloat162_rn(pa1.x - __low2float(h2), pa1.y - __high2float(h2));
            *(__nv_bfloat162*)&Al[buf][ar1][ac * 4 + 2] =
                __floats2bfloat162_rn(pa1.z - __low2float(h3), pa1.w - __high2float(h3));
            ss += pb.x * pb.x + pb.y * pb.y + pb.z * pb.z + pb.w * pb.w;
            __nv_bfloat162 g0 = __floats2bfloat162_rn(pb.x, pb.y);
            __nv_bfloat162 g1 = __floats2bfloat162_rn(pb.z, pb.w);
            *(__nv_bfloat162*)&Bh[buf][br][bc * 4]     = g0;
            *(__nv_bfloat162*)&Bh[buf][br][bc * 4 + 2] = g1;
            *(__nv_bfloat162*)&Bl[buf][br][bc * 4] =
                __floats2bfloat162_rn(pb.x - __low2float(g0), pb.y - __high2float(g0));
            *(__nv_bfloat162*)&Bl[buf][br][bc * 4 + 2] =
                __floats2bfloat162_rn(pb.z - __low2float(g1), pb.w - __high2float(g1));
        }

        // ---- issue LDG for stage s+1 BEFORE the barrier (no smem dependence) ----
        if (s + 1 < NSTG) {
            int k0 = kbase + (s + 1) * KC;
            pa0 = *(const float4*)(q + (size_t)ar0 * D + k0 + ac * 4);
            pa1 = *(const float4*)(q + (size_t)ar1 * D + k0 + ac * 4);
            pb = make_float4(0.f, 0.f, 0.f, 0.f);
            if (bg < M) pb = *(const float4*)(mc + (size_t)bg * D + k0 + bc * 4);
        }
        __syncthreads();

        // ---- MMA on buf (one k16 step) ----
        {
            int kk = tig * 2;
            unsigned ah[2][4], al[2][4], bh[4][2], bl[4][2];
#pragma unroll
            for (int mi = 0; mi < 2; mi++) {
                int r = warp_m * 32 + mi * 16 + quad;
                ah[mi][0] = *(const unsigned*)&Ah[buf][r][kk];
                ah[mi][1] = *(const unsigned*)&Ah[buf][r + 8][kk];
                ah[mi][2] = *(const unsigned*)&Ah[buf][r][kk + 8];
                ah[mi][3] = *(const unsigned*)&Ah[buf][r + 8][kk + 8];
                al[mi][0] = *(const unsigned*)&Al[buf][r][kk];
                al[mi][1] = *(const unsigned*)&Al[buf][r + 8][kk];
                al[mi][2] = *(const unsigned*)&Al[buf][r][kk + 8];
                al[mi][3] = *(const unsigned*)&Al[buf][r + 8][kk + 8];
            }
#pragma unroll
            for (int ni = 0; ni < 4; ni++) {
                int n = warp_n * 32 + ni * 8 + quad;
                bh[ni][0] = *(const unsigned*)&Bh[buf][n][kk];
                bh[ni][1] = *(const unsigned*)&Bh[buf][n][kk + 8];
                bl[ni][0] = *(const unsigned*)&Bl[buf][n][kk];
                bl[ni][1] = *(const unsigned*)&Bl[buf][n][kk + 8];
            }
#pragma unroll
            for (int mi = 0; mi < 2; mi++)
#pragma unroll
                for (int ni = 0; ni < 4; ni++) {
                    mma_bf16(acc[mi][ni], ah[mi], bh[ni]);   // hi*hi
                    mma_bf16(acc[mi][ni], ah[mi], bl[ni]);   // hi*lo
                    mma_bf16(acc[mi][ni], al[mi], bh[ni]);   // lo*hi
                }
        }
    }
    __syncthreads();

    // ---- msq: reduce over 4 loader lanes sharing B row (lanes differ in t&3) ----
    ss += __shfl_xor_sync(0xffffffffu, ss, 1);
    ss += __shfl_xor_sync(0xffffffffu, ss, 2);
    if (bc == 0 && bg < M) g_msq[kz][bg] = ss;

    // ---- epilogue ----
    float* dst = &g_cosp[kz][0];
#pragma unroll
    for (int mi = 0; mi < 2; mi++) {
        int r = warp_m * 32 + mi * 16 + quad;
#pragma unroll
        for (int ni = 0; ni < 4; ni++) {
            int col = n0 + warp_n * 32 + ni * 8 + tig * 2;
            if (col < M) {
                *(float2*)&dst[(size_t)r * M + col]       = make_float2(acc[mi][ni][0], acc[mi][ni][1]);
                *(float2*)&dst[(size_t)(r + 8) * M + col] = make_float2(acc[mi][ni][2], acc[mi][ni][3]);
            }
        }
    }
}

// ---------------- 2) top-50: 2-level radix threshold + exact candidate rank ------
#define CANDCAP 256
#define TKT 512     // topk threads

__device__ __forceinline__ unsigned key_of(float v) {
    unsigned u = __float_as_uint(v);
    return (u & 0x80000000u) ? ~u : (u | 0x80000000u);   // monotonic flip
}
__device__ __forceinline__ float val_of(unsigned k) {
    unsigned u = (k & 0x80000000u) ? (k & 0x7fffffffu) : ~k;
    return __uint_as_float(u);
}

__global__ __launch_bounds__(TKT) void topk_kernel(const float* __restrict__ q) {
    __shared__ unsigned keys[M];            // 25.2 KB
    __shared__ int suf[257];
    __shared__ unsigned s_prefix;
    __shared__ int s_remaining;
    __shared__ int s_candcnt;
    __shared__ unsigned cand_k[CANDCAP];
    __shared__ int cand_i[CANDCAP];
    __shared__ int fin_idx[TOPK];
    __shared__ float fin_val[TOPK];
    __shared__ float fin_e[TOPK];
    __shared__ float s_sum;
    __shared__ float s_qred[4];
    __shared__ float s_qi;

    int b = blockIdx.x, t = threadIdx.x;

    // q row norm for this batch
    {
        float ssq = 0.f;
        if (t < 128) {
            float4 v = ((const float4*)(q + (size_t)b * D))[t];
            ssq = v.x * v.x + v.y * v.y + v.z * v.z + v.w * v.w;
        }
#pragma unroll
        for (int o = 16; o > 0; o >>= 1) ssq += __shfl_xor_sync(0xffffffffu, ssq, o);
        if (t < 128 && (t & 31) == 0) s_qred[t >> 5] = ssq;
        __syncthreads();
        if (t == 0) {
            float tot = (s_qred[0] + s_qred[1]) + (s_qred[2] + s_qred[3]);
            s_qi = 1.0f / fmaxf(sqrtf(tot), CEPS);
        }
        __syncthreads();
    }
    float qi = s_qi;

    for (int i = t; i < M; i += TKT) {
        float d = (g_cosp[0][(size_t)b * M + i] + g_cosp[1][(size_t)b * M + i])
                + (g_cosp[2][(size_t)b * M + i] + g_cosp[3][(size_t)b * M + i]);
        float m = (g_msq[0][i] + g_msq[1][i]) + (g_msq[2][i] + g_msq[3][i]);
        float minv = 1.0f / fmaxf(sqrtf(m), CEPS);
        keys[i] = key_of(d * qi * minv);
    }
    if (t == 0) { s_prefix = 0u; s_remaining = TOPK; s_candcnt = 0; }
    __syncthreads();

    // ---- 2 radix levels: exact top-16-bit threshold prefix ----
#pragma unroll
    for (int level = 0; level < 2; level++) {
        int shift = 24 - level * 8;
        if (t < 257) suf[t] = 0;
        __syncthreads();
        unsigned pfx = s_prefix;
        for (int i = t; i < M; i += TKT) {
            unsigned k = keys[i];
            bool in = (level == 0) || ((k >> 24) == pfx);
            if (in) atomicAdd(&suf[(k >> shift) & 255], 1);
        }
        __syncthreads();
        if (t < 32) {           // warp 0: suffix scan of 256 bins
            int loc[8];
            int run = 0;
#pragma unroll
            for (int j = 7; j >= 0; j--) { run += suf[t * 8 + j]; loc[j] = run; }
            int x = run;
#pragma unroll
            for (int o = 1; o < 32; o <<= 1) {
                int y = __shfl_down_sync(0xffffffffu, x, o);
                if (t + o < 32) x += y;
            }
            int excl = x - run;
#pragma unroll
            for (int j = 0; j < 8; j++) suf[t * 8 + j] = loc[j] + excl;
        }
        __syncthreads();
        int rem = s_remaining;
        if (t < 256 && suf[t] >= rem && suf[t + 1] < rem) {
            s_prefix = (s_prefix << 8) | (unsigned)t;
            s_remaining = rem - suf[t + 1];
        }
        __syncthreads();
    }

    // ---- collect candidates: 16-bit prefix >= threshold prefix ----
    unsigned T16 = s_prefix;
    for (int i = t; i < M; i += TKT) {
        unsigned k = keys[i];
        if ((k >> 16) >= T16) {
            int p = atomicAdd(&s_candcnt, 1);
            if (p < CANDCAP) { cand_k[p] = k; cand_i[p] = i; }
        }
    }
    __syncthreads();
    int nc = min(s_candcnt, CANDCAP);

    // ---- exact rank among candidates by (key desc, idx asc); take rank < 50 ----
    if (t < nc) {
        unsigned mk = cand_k[t]; int mi = cand_i[t];
        int rank = 0;
        for (int j = 0; j < nc; j++) {
            unsigned ok = cand_k[j]; int oi = cand_i[j];
            if (ok > mk || (ok == mk && oi < mi)) rank++;
        }
        if (rank < TOPK) {
            fin_idx[rank] = mi;
            fin_val[rank] = val_of(mk);
        }
    }
    __syncthreads();
    if (t < TOPK) fin_e[t] = expf(fin_val[t] - fin_val[0]);
    __syncthreads();
    if (t == 0) {
        float s = 0.f;
        for (int kk = 0; kk < TOPK; kk++) s += fin_e[kk];
        s_sum = 1.0f / s;
    }
    __syncthreads();
    if (t < TOPK) {
        g_tidx[b * TOPK + t] = fin_idx[t];
        g_tw[b * TOPK + t]   = fin_e[t] * s_sum;
    }
}

// ---------------- 3) weighted block gather + blend (l-major, MLP batched) ----
__global__ __launch_bounds__(128) void gather_kernel(const float* __restrict__ enc,
                                                     const float* __restrict__ fp,
                                                     const float* __restrict__ weight,
                                                     float* __restrict__ out) {
    __shared__ const float4* s_p[TOPK];
    __shared__ float s_w[TOPK];
    int b = blockIdx.x & (NB - 1);     // fast dim: batch -> concurrent CTAs share l
    int l = blockIdx.x >> 7;           // slow dim: row within block
    int t = threadIdx.x;               // 128 threads x float4 = 512 floats
    if (t < TOPK) {
        s_p[t] = (const float4*)(fp + ((size_t)g_tidx[b * TOPK + t] * BLKR + l) * D);
        s_w[t] = g_tw[b * TOPK + t];
    }
    __syncthreads();

    float ax = 0.f, ay = 0.f, az = 0.f, aw = 0.f;
#pragma unroll
    for (int kk = 0; kk < TOPK; kk += 10) {
        float4 v[10];
#pragma unroll
        for (int u = 0; u < 10; u++) v[u] = s_p[kk + u][t];
#pragma unroll
        for (int u = 0; u < 10; u++) {
            float w = s_w[kk + u];
            ax += w * v[u].x; ay += w * v[u].y; az += w * v[u].z; aw += w * v[u].w;
        }
    }

    float wm = weight[0];
    float em = 1.f - wm;
    size_t off = ((size_t)b * BLKR + l) * D;
    float4 e = ((const float4*)(enc + off))[t];
    float4 o;
    o.x = ax * wm + e.x * em;
    o.y = ay * wm + e.y * em;
    o.z = az * wm + e.z * em;
    o.w = aw * wm + e.w * em;
    ((float4*)(out + off))[t] = o;
}

// ---------------- launch ----------------
extern "C" void kernel_launch(void* const* d_in, const int* in_sizes, int n_in,
                              void* d_out, int out_size) {
    const float* enc = (const float*)d_in[0];   // [128, 64, 512]
    const float* q   = (const float*)d_in[1];   // [128, 512]
    const float* mc  = (const float*)d_in[2];   // [6304, 512]
    const float* fp  = (const float*)d_in[3];   // [403456, 512]
    const float* w   = (const float*)d_in[4];   // [1]
    float* out = (float*)d_out;                 // [128, 64, 512]

    cos_gemm_kernel<<<dim3(NBLK, KSPLIT), 256>>>(q, mc);
    topk_kernel<<<NB, TKT>>>(q);
    gather_kernel<<<NB * BLKR, 128>>>(enc, fp, w, out);
}